// round 15
// baseline (speedup 1.0000x reference)
#include <cuda_runtime.h>
#include <math.h>

#define NEG_INF_VAL -10000000000.0f

namespace {
constexpr int Hc = 512;
constexpr int Sc = 1024;
constexpr int KS = 8;          // split-K for H=512 GEMMs
constexpr int SLICES = 16;     // attn slices per beam
constexpr int NPART = 64 * SLICES;  // 1024

// float scratch offsets
constexpr int OFF_GIP     = 0;                          // KS*64*1536
constexpr int OFF_GHP     = OFF_GIP + KS * 64 * 1536;
constexpr int OFF_QP      = OFF_GHP + KS * 64 * 1536;   // 64*512 (atomic-accumulated)
constexpr int OFF_HNEW    = OFF_QP + 64 * 512;
constexpr int OFF_QB1     = OFF_HNEW + 64 * 512;
constexpr int OFF_ATTN    = OFF_QB1 + 64;               // 64x1024
constexpr int OFF_PARTM   = OFF_ATTN + 64 * 1024;
constexpr int OFF_PARTL   = OFF_PARTM + NPART;
constexpr int OFF_PARTACC = OFF_PARTL + NPART;          // 1024*512
constexpr int OFF_CTXRAW  = OFF_PARTACC + NPART * 512;
constexpr int OFF_CTX     = OFF_CTXRAW + 64 * 512;
constexpr int OFF_RESULT  = OFF_CTX + 64 * 512;
constexpr int OFF_TKLOG   = OFF_RESULT + 64 * 512;
constexpr int SCR_TOTAL   = OFF_TKLOG + 256;

// output layout (floats), tuple members concatenated in order
constexpr int O_RESULT = 0;
constexpr int O_HIDDEN = 32768;
constexpr int O_IDX    = 65536;
constexpr int O_ATTNS  = 65792;
constexpr int O_MASK   = 327936;
constexpr int O_SCORES = 393472;
}

__device__ __align__(16) float g_scr[SCR_TOTAL];
__device__ int g_tkidx[256];
__device__ int g_cnt[64];      // per-beam attn-slice counters (zeroed by k_gate)
__device__ int g_cnt_ctx[8];   // per-CTX-col-block completion (zeroed by k_gate)
__device__ int g_cnt_res;      // res-tile completion (zeroed by k_gate)

// wait for the programmatically-linked predecessor kernel to fully complete
__device__ __forceinline__ void dep_sync() {
#if __CUDA_ARCH__ >= 900
    cudaGridDependencySynchronize();
#endif
}

// ---------------- GEMM tiles (64 rows x 64 cols, K-chunk = ITERS*32) ----------------
// LDCGA: read A via __ldcg (A produced by other blocks of the SAME kernel)
template<int ITERS, bool ATOMIC, bool LDCGA>
__device__ __forceinline__ void gemm_bt_tile(const float* __restrict__ A, int lda,
                                             const float* __restrict__ B, int ldb,
                                             float* __restrict__ C, int ldc,
                                             const float* __restrict__ bias, bool addBias,
                                             int j0, int k0,
                                             float (*As)[65], float (*Bs)[65]) {
    const int t = threadIdx.x;
    const int bx = (t & 15) * 4;
    const int by = (t >> 4) * 4;
    float acc[4][4] = {};
#pragma unroll
    for (int it = 0; it < ITERS; it++) {
        const int kk = k0 + it * 32;
#pragma unroll
        for (int i = 0; i < 8; i++) {
            int idx = t + i * 256;
            int r = idx >> 5, c = idx & 31;
            As[c][r] = LDCGA ? __ldcg(&A[r * lda + kk + c]) : A[r * lda + kk + c];
            Bs[c][r] = B[(j0 + r) * ldb + kk + c];
        }
        __syncthreads();
#pragma unroll
        for (int c = 0; c < 32; c++) {
            float b0 = Bs[c][bx + 0], b1 = Bs[c][bx + 1], b2 = Bs[c][bx + 2], b3 = Bs[c][bx + 3];
#pragma unroll
            for (int r = 0; r < 4; r++) {
                float av = As[c][by + r];
                acc[r][0] += av * b0; acc[r][1] += av * b1;
                acc[r][2] += av * b2; acc[r][3] += av * b3;
            }
        }
        __syncthreads();
    }
#pragma unroll
    for (int r = 0; r < 4; r++)
#pragma unroll
        for (int cc = 0; cc < 4; cc++) {
            float v = acc[r][cc];
            if (addBias) v += bias[j0 + bx + cc];
            if (ATOMIC) atomicAdd(&C[(by + r) * ldc + j0 + bx + cc], v);
            else        C[(by + r) * ldc + j0 + bx + cc] = v;
        }
}

template<int ITERS, bool ATOMIC>
__device__ __forceinline__ void gemm_ab_tile(const float* __restrict__ A, int lda,
                                             const float* __restrict__ B, int ldb,
                                             float* __restrict__ C, int ldc,
                                             int j0, int k0,
                                             float (*As)[65], float (*Bs)[65]) {
    const int t = threadIdx.x;
    const int bx = (t & 15) * 4;
    const int by = (t >> 4) * 4;
    float acc[4][4] = {};
#pragma unroll
    for (int it = 0; it < ITERS; it++) {
        const int kk = k0 + it * 32;
#pragma unroll
        for (int i = 0; i < 8; i++) {
            int idx = t + i * 256;
            int r = idx >> 5, c = idx & 31;
            As[c][r] = A[r * lda + kk + c];
        }
#pragma unroll
        for (int i = 0; i < 8; i++) {
            int idx = t + i * 256;
            int c = idx >> 6, jj = idx & 63;
            Bs[c][jj] = B[(kk + c) * ldb + j0 + jj];
        }
        __syncthreads();
#pragma unroll
        for (int c = 0; c < 32; c++) {
            float b0 = Bs[c][bx + 0], b1 = Bs[c][bx + 1], b2 = Bs[c][bx + 2], b3 = Bs[c][bx + 3];
#pragma unroll
            for (int r = 0; r < 4; r++) {
                float av = As[c][by + r];
                acc[r][0] += av * b0; acc[r][1] += av * b1;
                acc[r][2] += av * b2; acc[r][3] += av * b3;
            }
        }
        __syncthreads();
    }
#pragma unroll
    for (int r = 0; r < 4; r++)
#pragma unroll
        for (int cc = 0; cc < 4; cc++) {
            if (ATOMIC) atomicAdd(&C[(by + r) * ldc + j0 + bx + cc], acc[r][cc]);
            else        C[(by + r) * ldc + j0 + bx + cc] = acc[r][cc];
        }
}

// ---- gi/gh partials: grid (24, KS, 2), block 256 ----
__global__ void __launch_bounds__(256) k_gru(const float* __restrict__ x, const float* __restrict__ h,
                                             const float* __restrict__ wih, const float* __restrict__ whh) {
    __shared__ float As[32][65];
    __shared__ float Bs[32][65];
    const float* A = blockIdx.z ? h : x;
    const float* B = blockIdx.z ? whh : wih;
    float* C = g_scr + (blockIdx.z ? OFF_GHP : OFF_GIP) + blockIdx.y * (64 * 1536);
    gemm_bt_tile<2, false, false>(A, Hc, B, Hc, C, 1536, nullptr, false,
                                  blockIdx.x * 64, blockIdx.y * 64, As, Bs);
}

// ---- GRU gates + qb1 + zero RESULT/QP + zero all counters: grid 64, block 512 ----
__global__ void __launch_bounds__(512) k_gate(const float* __restrict__ lh, const float* __restrict__ bih,
                                              const float* __restrict__ bhh, const float* __restrict__ b1) {
    int b = blockIdx.x, j = threadIdx.x;
    dep_sync();   // wait for k_gru partials
    if (j == 0) g_cnt[b] = 0;
    if (b == 0 && j < 8) g_cnt_ctx[j] = 0;
    if (b == 0 && j == 8) g_cnt_res = 0;
    float gir = bih[j],        ghr = bhh[j];
    float giz = bih[512 + j],  ghz = bhh[512 + j];
    float gin = bih[1024 + j], ghn = bhh[1024 + j];
#pragma unroll
    for (int p = 0; p < KS; p++) {
        const float* gi = g_scr + OFF_GIP + p * (64 * 1536) + b * 1536;
        const float* gh = g_scr + OFF_GHP + p * (64 * 1536) + b * 1536;
        gir += gi[j];        ghr += gh[j];
        giz += gi[512 + j];  ghz += gh[512 + j];
        gin += gi[1024 + j]; ghn += gh[1024 + j];
    }
    float r = 1.f / (1.f + expf(-(gir + ghr)));
    float z = 1.f / (1.f + expf(-(giz + ghz)));
    float n = tanhf(gin + r * ghn);
    float hv = lh[b * Hc + j];
    float hn = (1.f - z) * n + z * hv;
    g_scr[OFF_HNEW + b * Hc + j] = hn;
    g_scr[OFF_RESULT + b * Hc + j] = 0.f;   // zero accumulator for result adds
    g_scr[OFF_QP + b * Hc + j] = 0.f;       // zero accumulator for q atomics

    float p = hn * b1[j];
    __shared__ float red[16];
#pragma unroll
    for (int o = 16; o; o >>= 1) p += __shfl_xor_sync(0xffffffffu, p, o);
    if ((j & 31) == 0) red[j >> 5] = p;
    __syncthreads();
    if (j < 16) {
        float v = red[j];
#pragma unroll
        for (int o = 8; o; o >>= 1) v += __shfl_xor_sync(0x0000ffffu, v, o);
        if (j == 0) g_scr[OFF_QB1 + b] = v;
    }
}

// ---- q (z=0, atomic into QP) + RESULT += hnew @ w3[:,512:]^T + b3 (z=1): grid (8, KS, 2) ----
__global__ void __launch_bounds__(256) k_q2(const float* __restrict__ w1,
                                            const float* __restrict__ w3,
                                            const float* __restrict__ b3) {
    __shared__ float As[32][65];
    __shared__ float Bs[32][65];
    dep_sync();   // wait for k_gate (HNEW + zeroed QP/RESULT)
    if (blockIdx.z == 0) {
        gemm_ab_tile<2, true>(g_scr + OFF_HNEW, Hc, w1, Hc,
                              g_scr + OFF_QP, Hc,
                              blockIdx.x * 64, blockIdx.y * 64, As, Bs);
    } else {
        gemm_bt_tile<2, true, false>(g_scr + OFF_HNEW, Hc, w3 + 512, 1024,
                                     g_scr + OFF_RESULT, Hc, b3, blockIdx.y == 0,
                                     blockIdx.x * 64, blockIdx.y * 64, As, Bs);
    }
}

// ================= ATTN + fused combine/top-4 ===========
// grid 1024 (16 slices/beam), block 256, 64 rows/block in 16 chunks of 4 rows (R14 body).
// Last-arriving slice block of each beam performs the combine + top-4 + TKLOG.
__device__ __forceinline__ void cp_prefetch4(float4* dst, const float4* src, int t) {
#pragma unroll
    for (int i = 0; i < 2; i++) {
        unsigned d = (unsigned)__cvta_generic_to_shared(dst + t + i * 256);
        asm volatile("cp.async.cg.shared.global [%0], [%1], 16;\n" :: "r"(d), "l"(src + t + i * 256));
    }
    asm volatile("cp.async.commit_group;\n");
}

__global__ void __launch_bounds__(256, 8) k_attn(const float* __restrict__ enc,
                                                 const float* __restrict__ mask,
                                                 const float* __restrict__ evid) {
    constexpr float inv_div = 0.04419417382415922f;  // 1/sqrt(512)
    __shared__ float qs[512];
    __shared__ float4 buf[2][512];   // 2 x (4 rows x 512 f32) = 16KB (>= 1024 floats for sv reuse)
    __shared__ float scs[4];
    __shared__ float ws[4];
    __shared__ float smask[64];
    __shared__ float e_sh[16];
    __shared__ int   s_last;
    __shared__ int   pick[4];
    __shared__ float pickv[4];
    __shared__ float wvv[8];
    __shared__ int   wii[8];

    const int t = threadIdx.x;
    const int b = blockIdx.x >> 4;
    const int slice = blockIdx.x & 15;
    const int sbase = slice * 64;
    const float* encb = enc + (size_t)b * Sc * Hc;

    // first chunk prefetch + mask staging touch only kernel inputs — issue before the dep wait
    cp_prefetch4(buf[0], reinterpret_cast<const float4*>(encb + (size_t)sbase * Hc), t);
    if (t < 64) smask[t] = mask[b * Sc + sbase + t];

    dep_sync();   // wait for k_q2 (QP, QB1)

    qs[t]       = g_scr[OFF_QP + b * Hc + t] * inv_div;
    qs[t + 256] = g_scr[OFF_QP + b * Hc + t + 256] * inv_div;
    const float cb = g_scr[OFF_QB1 + b] * inv_div;

    const int w = t >> 5, lane = t & 31;
    float m = -INFINITY, l = 0.f, a0 = 0.f, a1 = 0.f;

    for (int c = 0; c < 16; c++) {
        asm volatile("cp.async.wait_group 0;\n");
        __syncthreads();   // chunk c ready AND all threads done with buf[(c+1)&1]

        if (c < 15)
            cp_prefetch4(buf[(c + 1) & 1],
                         reinterpret_cast<const float4*>(encb + (size_t)(sbase + (c + 1) * 4) * Hc), t);

        const float* ch = reinterpret_cast<const float*>(buf[c & 1]);
        const int s0 = sbase + c * 4;

        // scores: warps 0-3 each compute one row
        if (w < 4) {
            float d = 0.f;
#pragma unroll
            for (int kk = 0; kk < 16; kk++) {
                int k = lane + kk * 32;
                d += ch[w * 512 + k] * qs[k];
            }
#pragma unroll
            for (int o = 16; o; o >>= 1) d += __shfl_xor_sync(0xffffffffu, d, o);
            if (lane == 0) {
                float sc = d + cb + smask[c * 4 + w];
                scs[w] = sc;
                g_scr[OFF_ATTN + b * Sc + s0 + w] = sc;
            }
        }
        __syncthreads();

        float cm = fmaxf(fmaxf(scs[0], scs[1]), fmaxf(scs[2], scs[3]));
        float nm = fmaxf(m, cm);
        if (nm > m) {
            float scale = expf(m - nm);
            a0 *= scale; a1 *= scale; l *= scale;
        }
        if (t < 4) ws[t] = expf(scs[t] - nm);
        __syncthreads();

        float lsum = 0.f;
#pragma unroll
        for (int r = 0; r < 4; r++) {
            float wr = ws[r];
            lsum += wr;
            a0 += wr * ch[r * 512 + t];
            a1 += wr * ch[r * 512 + t + 256];
        }
        l += lsum;
        m = nm;
        // next iteration's first sync protects ch/ws/scs
    }
    const int pid = blockIdx.x;
    if (t == 0) { g_scr[OFF_PARTM + pid] = m; g_scr[OFF_PARTL + pid] = l; }
    g_scr[OFF_PARTACC + pid * 512 + t]       = a0;
    g_scr[OFF_PARTACC + pid * 512 + t + 256] = a1;

    // ---- last-arriving slice block of this beam: combine + top-4 + TKLOG ----
    __threadfence();
    if (t == 0) s_last = (atomicAdd(&g_cnt[b], 1) == SLICES - 1);
    __syncthreads();
    if (!s_last) return;

    float M = -INFINITY;
#pragma unroll
    for (int p = 0; p < SLICES; p++)
        M = fmaxf(M, __ldcg(&g_scr[OFF_PARTM + b * SLICES + p]));
    if (t < SLICES)
        e_sh[t] = expf(__ldcg(&g_scr[OFF_PARTM + b * SLICES + t]) - M);
    __syncthreads();

    float L = 0.f;
#pragma unroll
    for (int p = 0; p < SLICES; p++)
        L += __ldcg(&g_scr[OFF_PARTL + b * SLICES + p]) * e_sh[p];
    float invL = 1.f / L;

#pragma unroll
    for (int half = 0; half < 2; half++) {
        int col = t + half * 256;
        float s = 0.f;
#pragma unroll
        for (int p = 0; p < SLICES; p++)
            s += e_sh[p] * __ldcg(&g_scr[OFF_PARTACC + (b * SLICES + p) * 512 + col]);
        g_scr[OFF_CTXRAW + b * Hc + col] = s * invL;
        g_scr[OFF_CTX + b * Hc + col] = 0.f;   // zero atomic target for ctx GEMM
    }

    // top-4 over this beam's scores (cp.async fully drained; reuse buf as sv[1024])
    float* sv = reinterpret_cast<float*>(buf);
#pragma unroll
    for (int i = 0; i < 4; i++)
        sv[t + i * 256] = __ldcg(&g_scr[OFF_ATTN + b * Sc + t + i * 256]);
    __syncthreads();
    for (int round = 0; round < 4; round++) {
        float best = -INFINITY;
        int bi = 0x7fffffff;
#pragma unroll
        for (int u = 0; u < 4; u++) {
            int idx = t * 4 + u;
            bool skip = false;
            for (int rr = 0; rr < round; rr++) skip |= (pick[rr] == idx);
            float v = sv[idx];
            if (!skip && (v > best || (v == best && idx < bi))) { best = v; bi = idx; }
        }
#pragma unroll
        for (int o = 16; o; o >>= 1) {
            float ov = __shfl_xor_sync(0xffffffffu, best, o);
            int   oi = __shfl_xor_sync(0xffffffffu, bi, o);
            if (ov > best || (ov == best && oi < bi)) { best = ov; bi = oi; }
        }
        if (lane == 0) { wvv[w] = best; wii[w] = bi; }
        __syncthreads();
        if (t == 0) {
            float bb = wvv[0]; int bj = wii[0];
            for (int k = 1; k < 8; k++)
                if (wvv[k] > bb || (wvv[k] == bb && wii[k] < bj)) { bb = wvv[k]; bj = wii[k]; }
            pick[round] = bj; pickv[round] = bb;
        }
        __syncthreads();
    }
    if (t < 4) {
        g_scr[OFF_TKLOG + b * 4 + t] = (M - pickv[t]) + logf(L) + evid[b];
        g_tkidx[b * 4 + t] = pick[t];
    }
}

// ================= TAIL: ctx (0-63) | res (64-127, spin) | gather (128-895) ==========
__global__ void __launch_bounds__(256) k_tail(
        const int* __restrict__ esi, const float* __restrict__ prev_scores,
        const float* __restrict__ mask, const float* __restrict__ w2,
        const float* __restrict__ b2, const float* __restrict__ w3,
        float* __restrict__ out) {
    __shared__ float As[32][65];
    __shared__ float Bs[32][65];
    __shared__ int ssels[64];
    __shared__ int ssent[64];
    const int t = threadIdx.x, bid = blockIdx.x;
    const int lane = t & 31, w = t >> 5;

    dep_sync();   // wait for k_attn (partials, CTXRAW, zeroed CTX, TKLOG, ATTN)

    if (bid < 64) {
        // ctx tile: CTX += ctxraw @ w2^T + b2
        int jt = bid >> 3, kt = bid & 7;
        gemm_bt_tile<2, true, false>(g_scr + OFF_CTXRAW, Hc, w2, Hc,
                                     g_scr + OFF_CTX, Hc, b2, kt == 0,
                                     jt * 64, kt * 64, As, Bs);
        __threadfence();
        __syncthreads();
        if (t == 0) atomicAdd(&g_cnt_ctx[jt], 1);
        return;
    }
    if (bid < 128) {
        // res tile: RESULT += CTX @ w3[:, :512]^T ; A (CTX) produced in this kernel -> ldcg + spin
        int j = bid - 64;
        int jt = j >> 3, kt = j & 7;
        if (t == 0) {
            while (__ldcg((const int*)&g_cnt_ctx[kt]) < 8) __nanosleep(64);
        }
        __syncthreads();
        gemm_bt_tile<2, true, true>(g_scr + OFF_CTX, Hc, w3, 1024,
                                    g_scr + OFF_RESULT, Hc, nullptr, false,
                                    jt * 64, kt * 64, As, Bs);
        __threadfence();
        __syncthreads();
        if (t == 0) atomicAdd(&g_cnt_res, 1);
        return;
    }

    // ---- gather: blocks 128..895 (768), each thread handles i and i+196608 ----
    const int gb = bid - 128;

    // beam selection (redundant per block; 8 warps x 2 batches)
#pragma unroll
    for (int it2 = 0; it2 < 2; it2++) {
        int wb = w * 2 + it2;
        float v = (lane < 16) ? g_scr[OFF_TKLOG + wb * 16 + lane] : INFINITY;
        int rank = 0;
#pragma unroll
        for (int jj = 0; jj < 16; jj++) {
            float vj = __shfl_sync(0xffffffffu, v, jj);
            rank += (vj < v) || (vj == v && jj < lane);
        }
        if (lane < 16 && rank < 4) {
            int k = wb * 4 + rank;
            int s = wb * 4 + (lane >> 2);
            int rr = lane & 3;
            int sent = g_tkidx[s * 4 + rr];
            ssels[k] = s;
            ssent[k] = sent;
            if (gb == 0) {
                out[O_SCORES + k] = v;
                out[O_IDX + k * 4 + 0] = (float)esi[s * 3 + 0];
                out[O_IDX + k * 4 + 1] = (float)esi[s * 3 + 1];
                out[O_IDX + k * 4 + 2] = (float)esi[s * 3 + 2];
                out[O_IDX + k * 4 + 3] = (float)sent;
            }
        }
    }

    // blocks touching RESULT (gb < 128 -> i < 32768) wait for all res tiles
    if (gb < 128) {
        if (t == 0) {
            while (__ldcg((const int*)&g_cnt_res) < 64) __nanosleep(64);
        }
    }
    __syncthreads();

#pragma unroll
    for (int half = 0; half < 2; half++) {
        int i = gb * 256 + t + half * 196608;
        if (i < 32768) {
            int bi = i >> 9, jj = i & 511;
            out[O_RESULT + i] = __ldcg(&g_scr[OFF_RESULT + ssels[bi] * 512 + jj]);
        } else if (i < 65536) {
            int jj = i - 32768;
            out[O_HIDDEN + jj] = g_scr[OFF_HNEW + ssels[jj >> 9] * 512 + (jj & 511)];
        } else if (i < 327680) {
            int jj = i - 65536;
            int p = jj >> 16;
            int rem = jj & 65535;
            int bi = rem >> 10, scol = rem & 1023;
            int s = ssels[bi];
            float v = (p < 3) ? prev_scores[p * 65536 + s * 1024 + scol]
                              : g_scr[OFF_ATTN + s * 1024 + scol];
            out[O_ATTNS + jj] = v;
        } else {
            int jj = i - 327680;
            int bi = jj >> 10, scol = jj & 1023;
            int s = ssels[bi];
            float v = (scol == ssent[bi]) ? NEG_INF_VAL : mask[s * 1024 + scol];
            out[O_MASK + jj] = v;
        }
    }
}

// ---------------- launch helpers ----------------
static inline void launch_pdl(const void* func, dim3 grid, dim3 block, void** args) {
    cudaLaunchConfig_t cfg = {};
    cfg.gridDim = grid;
    cfg.blockDim = block;
    cfg.dynamicSmemBytes = 0;
    cfg.stream = 0;
    cudaLaunchAttribute attr[1];
    attr[0].id = cudaLaunchAttributeProgrammaticStreamSerialization;
    attr[0].val.programmaticStreamSerializationAllowed = 1;
    cfg.attrs = attr;
    cfg.numAttrs = 1;
    cudaLaunchKernelExC(&cfg, func, args);
}

extern "C" void kernel_launch(void* const* d_in, const int* in_sizes, int n_in,
                              void* d_out, int out_size) {
    const float* last_hidden = (const float*)d_in[0];
    const float* dec_inputs  = (const float*)d_in[1];
    const float* enc         = (const float*)d_in[2];
    const float* prev_scores = (const float*)d_in[3];
    const float* mask        = (const float*)d_in[4];
    const float* evid        = (const float*)d_in[5];
    const int*   esi         = (const int*)d_in[6];
    const float* w1  = (const float*)d_in[7];
    const float* b1  = (const float*)d_in[8];
    const float* w2  = (const float*)d_in[9];
    const float* b2  = (const float*)d_in[10];
    const float* w3  = (const float*)d_in[11];
    const float* b3  = (const float*)d_in[12];
    const float* wih = (const float*)d_in[13];
    const float* whh = (const float*)d_in[14];
    const float* bih = (const float*)d_in[15];
    const float* bhh = (const float*)d_in[16];
    float* out = (float*)d_out;

    k_gru<<<dim3(24, KS, 2), 256>>>(dec_inputs, last_hidden, wih, whh);

    { void* a[] = {(void*)&last_hidden, (void*)&bih, (void*)&bhh, (void*)&b1};
      launch_pdl((const void*)k_gate, dim3(64), dim3(512), a); }
    { void* a[] = {(void*)&w1, (void*)&w3, (void*)&b3};
      launch_pdl((const void*)k_q2, dim3(8, KS, 2), dim3(256), a); }
    { void* a[] = {(void*)&enc, (void*)&mask, (void*)&evid};
      launch_pdl((const void*)k_attn, dim3(1024), dim3(256), a); }
    { void* a[] = {(void*)&esi, (void*)&prev_scores, (void*)&mask,
                   (void*)&w2, (void*)&b2, (void*)&w3, (void*)&out};
      launch_pdl((const void*)k_tail, dim3(896), dim3(256), a); }
}

// round 17
// speedup vs baseline: 1.0029x; 1.0029x over previous
#include <cuda_runtime.h>
#include <math.h>

#define NEG_INF_VAL -10000000000.0f

namespace {
constexpr int Hc = 512;
constexpr int Sc = 1024;
constexpr int KS = 8;          // split-K for H=512 GEMMs
constexpr int SLICES = 16;     // attn slices per beam
constexpr int NPART = 64 * SLICES;  // 1024

// float scratch offsets
constexpr int OFF_GIP     = 0;                          // KS*64*1536
constexpr int OFF_GHP     = OFF_GIP + KS * 64 * 1536;
constexpr int OFF_QP      = OFF_GHP + KS * 64 * 1536;   // 64*512 (atomic-accumulated)
constexpr int OFF_HNEW    = OFF_QP + 64 * 512;
constexpr int OFF_QB1     = OFF_HNEW + 64 * 512;
constexpr int OFF_ATTN    = OFF_QB1 + 64;               // 64x1024
constexpr int OFF_PARTM   = OFF_ATTN + 64 * 1024;
constexpr int OFF_PARTL   = OFF_PARTM + NPART;
constexpr int OFF_PARTACC = OFF_PARTL + NPART;          // 1024*512
constexpr int OFF_CTXRAW  = OFF_PARTACC + NPART * 512;
constexpr int OFF_CTX     = OFF_CTXRAW + 64 * 512;
constexpr int OFF_RESULT  = OFF_CTX + 64 * 512;
constexpr int OFF_TKLOG   = OFF_RESULT + 64 * 512;
constexpr int SCR_TOTAL   = OFF_TKLOG + 256;

// output layout (floats), tuple members concatenated in order
constexpr int O_RESULT = 0;
constexpr int O_HIDDEN = 32768;
constexpr int O_IDX    = 65536;
constexpr int O_ATTNS  = 65792;
constexpr int O_MASK   = 327936;
constexpr int O_SCORES = 393472;
}

__device__ __align__(16) float g_scr[SCR_TOTAL];
__device__ int g_tkidx[256];
__device__ int g_cnt_ctx[8];   // per-CTX-col-block completion (zeroed by k_gate)
__device__ int g_cnt_res;      // res-tile completion (zeroed by k_gate)

// wait for the programmatically-linked predecessor kernel to fully complete
__device__ __forceinline__ void dep_sync() {
#if __CUDA_ARCH__ >= 900
    cudaGridDependencySynchronize();
#endif
}

// ---------------- GEMM tiles (64 rows x 64 cols, K-chunk = ITERS*32) ----------------
// LDCGA: read A via __ldcg (A produced by other blocks of the SAME kernel)
template<int ITERS, bool ATOMIC, bool LDCGA>
__device__ __forceinline__ void gemm_bt_tile(const float* __restrict__ A, int lda,
                                             const float* __restrict__ B, int ldb,
                                             float* __restrict__ C, int ldc,
                                             const float* __restrict__ bias, bool addBias,
                                             int j0, int k0,
                                             float (*As)[65], float (*Bs)[65]) {
    const int t = threadIdx.x;
    const int bx = (t & 15) * 4;
    const int by = (t >> 4) * 4;
    float acc[4][4] = {};
#pragma unroll
    for (int it = 0; it < ITERS; it++) {
        const int kk = k0 + it * 32;
#pragma unroll
        for (int i = 0; i < 8; i++) {
            int idx = t + i * 256;
            int r = idx >> 5, c = idx & 31;
            As[c][r] = LDCGA ? __ldcg(&A[r * lda + kk + c]) : A[r * lda + kk + c];
            Bs[c][r] = B[(j0 + r) * ldb + kk + c];
        }
        __syncthreads();
#pragma unroll
        for (int c = 0; c < 32; c++) {
            float b0 = Bs[c][bx + 0], b1 = Bs[c][bx + 1], b2 = Bs[c][bx + 2], b3 = Bs[c][bx + 3];
#pragma unroll
            for (int r = 0; r < 4; r++) {
                float av = As[c][by + r];
                acc[r][0] += av * b0; acc[r][1] += av * b1;
                acc[r][2] += av * b2; acc[r][3] += av * b3;
            }
        }
        __syncthreads();
    }
#pragma unroll
    for (int r = 0; r < 4; r++)
#pragma unroll
        for (int cc = 0; cc < 4; cc++) {
            float v = acc[r][cc];
            if (addBias) v += bias[j0 + bx + cc];
            if (ATOMIC) atomicAdd(&C[(by + r) * ldc + j0 + bx + cc], v);
            else        C[(by + r) * ldc + j0 + bx + cc] = v;
        }
}

template<int ITERS, bool ATOMIC>
__device__ __forceinline__ void gemm_ab_tile(const float* __restrict__ A, int lda,
                                             const float* __restrict__ B, int ldb,
                                             float* __restrict__ C, int ldc,
                                             int j0, int k0,
                                             float (*As)[65], float (*Bs)[65]) {
    const int t = threadIdx.x;
    const int bx = (t & 15) * 4;
    const int by = (t >> 4) * 4;
    float acc[4][4] = {};
#pragma unroll
    for (int it = 0; it < ITERS; it++) {
        const int kk = k0 + it * 32;
#pragma unroll
        for (int i = 0; i < 8; i++) {
            int idx = t + i * 256;
            int r = idx >> 5, c = idx & 31;
            As[c][r] = A[r * lda + kk + c];
        }
#pragma unroll
        for (int i = 0; i < 8; i++) {
            int idx = t + i * 256;
            int c = idx >> 6, jj = idx & 63;
            Bs[c][jj] = B[(kk + c) * ldb + j0 + jj];
        }
        __syncthreads();
#pragma unroll
        for (int c = 0; c < 32; c++) {
            float b0 = Bs[c][bx + 0], b1 = Bs[c][bx + 1], b2 = Bs[c][bx + 2], b3 = Bs[c][bx + 3];
#pragma unroll
            for (int r = 0; r < 4; r++) {
                float av = As[c][by + r];
                acc[r][0] += av * b0; acc[r][1] += av * b1;
                acc[r][2] += av * b2; acc[r][3] += av * b3;
            }
        }
        __syncthreads();
    }
#pragma unroll
    for (int r = 0; r < 4; r++)
#pragma unroll
        for (int cc = 0; cc < 4; cc++) {
            if (ATOMIC) atomicAdd(&C[(by + r) * ldc + j0 + bx + cc], acc[r][cc]);
            else        C[(by + r) * ldc + j0 + bx + cc] = acc[r][cc];
        }
}

// ---- gi/gh partials: grid (24, KS, 2), block 256 ----
__global__ void __launch_bounds__(256) k_gru(const float* __restrict__ x, const float* __restrict__ h,
                                             const float* __restrict__ wih, const float* __restrict__ whh) {
    __shared__ float As[32][65];
    __shared__ float Bs[32][65];
    const float* A = blockIdx.z ? h : x;
    const float* B = blockIdx.z ? whh : wih;
    float* C = g_scr + (blockIdx.z ? OFF_GHP : OFF_GIP) + blockIdx.y * (64 * 1536);
    gemm_bt_tile<2, false, false>(A, Hc, B, Hc, C, 1536, nullptr, false,
                                  blockIdx.x * 64, blockIdx.y * 64, As, Bs);
}

// ---- GRU gates + qb1 + zero RESULT/QP + zero counters: grid 64, block 512 ----
__global__ void __launch_bounds__(512) k_gate(const float* __restrict__ lh, const float* __restrict__ bih,
                                              const float* __restrict__ bhh, const float* __restrict__ b1) {
    int b = blockIdx.x, j = threadIdx.x;
    dep_sync();   // wait for k_gru partials
    if (b == 0 && j < 8) g_cnt_ctx[j] = 0;
    if (b == 0 && j == 8) g_cnt_res = 0;
    float gir = bih[j],        ghr = bhh[j];
    float giz = bih[512 + j],  ghz = bhh[512 + j];
    float gin = bih[1024 + j], ghn = bhh[1024 + j];
#pragma unroll
    for (int p = 0; p < KS; p++) {
        const float* gi = g_scr + OFF_GIP + p * (64 * 1536) + b * 1536;
        const float* gh = g_scr + OFF_GHP + p * (64 * 1536) + b * 1536;
        gir += gi[j];        ghr += gh[j];
        giz += gi[512 + j];  ghz += gh[512 + j];
        gin += gi[1024 + j]; ghn += gh[1024 + j];
    }
    float r = 1.f / (1.f + expf(-(gir + ghr)));
    float z = 1.f / (1.f + expf(-(giz + ghz)));
    float n = tanhf(gin + r * ghn);
    float hv = lh[b * Hc + j];
    float hn = (1.f - z) * n + z * hv;
    g_scr[OFF_HNEW + b * Hc + j] = hn;
    g_scr[OFF_RESULT + b * Hc + j] = 0.f;   // zero accumulator for result adds
    g_scr[OFF_QP + b * Hc + j] = 0.f;       // zero accumulator for q atomics

    float p = hn * b1[j];
    __shared__ float red[16];
#pragma unroll
    for (int o = 16; o; o >>= 1) p += __shfl_xor_sync(0xffffffffu, p, o);
    if ((j & 31) == 0) red[j >> 5] = p;
    __syncthreads();
    if (j < 16) {
        float v = red[j];
#pragma unroll
        for (int o = 8; o; o >>= 1) v += __shfl_xor_sync(0x0000ffffu, v, o);
        if (j == 0) g_scr[OFF_QB1 + b] = v;
    }
}

// ---- q (z=0, atomic into QP) + RESULT += hnew @ w3[:,512:]^T + b3 (z=1): grid (8, KS, 2) ----
__global__ void __launch_bounds__(256) k_q2(const float* __restrict__ w1,
                                            const float* __restrict__ w3,
                                            const float* __restrict__ b3) {
    __shared__ float As[32][65];
    __shared__ float Bs[32][65];
    dep_sync();   // wait for k_gate (HNEW + zeroed QP/RESULT)
    if (blockIdx.z == 0) {
        gemm_ab_tile<2, true>(g_scr + OFF_HNEW, Hc, w1, Hc,
                              g_scr + OFF_QP, Hc,
                              blockIdx.x * 64, blockIdx.y * 64, As, Bs);
    } else {
        gemm_bt_tile<2, true, false>(g_scr + OFF_HNEW, Hc, w3 + 512, 1024,
                                     g_scr + OFF_RESULT, Hc, b3, blockIdx.y == 0,
                                     blockIdx.x * 64, blockIdx.y * 64, As, Bs);
    }
}

// ================= ATTN: streaming score + online softmax + context (float2 columns) ===========
// grid 1024 (16 slices/beam), block 256, 64 rows/block in 16 chunks of 4 rows.
// Thread t owns float2 column pair (2t, 2t+1). Single wave: 8 blocks/SM.
__device__ __forceinline__ void cp_prefetch4(float4* dst, const float4* src, int t) {
#pragma unroll
    for (int i = 0; i < 2; i++) {
        unsigned d = (unsigned)__cvta_generic_to_shared(dst + t + i * 256);
        asm volatile("cp.async.cg.shared.global [%0], [%1], 16;\n" :: "r"(d), "l"(src + t + i * 256));
    }
    asm volatile("cp.async.commit_group;\n");
}

__global__ void __launch_bounds__(256, 8) k_attn(const float* __restrict__ enc,
                                                 const float* __restrict__ mask) {
    constexpr float inv_div = 0.04419417382415922f;  // 1/sqrt(512)
    __shared__ float2 qs2[256];      // 2KB
    __shared__ float4 buf[2][512];   // 2 x (4 rows x 512 f32) = 16KB
    __shared__ float scs[4];
    __shared__ float ws[4];
    __shared__ float smask[64];

    const int t = threadIdx.x;
    const int b = blockIdx.x >> 4;
    const int slice = blockIdx.x & 15;
    const int sbase = slice * 64;
    const float* encb = enc + (size_t)b * Sc * Hc;

    // first chunk prefetch + mask staging touch only kernel inputs — issue before the dep wait
    cp_prefetch4(buf[0], reinterpret_cast<const float4*>(encb + (size_t)sbase * Hc), t);
    if (t < 64) smask[t] = mask[b * Sc + sbase + t];

    dep_sync();   // wait for k_q2 (QP, QB1)

    {
        float2 q = reinterpret_cast<const float2*>(g_scr + OFF_QP + b * Hc)[t];
        qs2[t] = make_float2(q.x * inv_div, q.y * inv_div);
    }
    const float cb = g_scr[OFF_QB1 + b] * inv_div;

    const int w = t >> 5, lane = t & 31;
    float m = -INFINITY, l = 0.f, ax = 0.f, ay = 0.f;

    for (int c = 0; c < 16; c++) {
        asm volatile("cp.async.wait_group 0;\n");
        __syncthreads();   // chunk c ready AND all threads done with buf[(c+1)&1]

        if (c < 15)
            cp_prefetch4(buf[(c + 1) & 1],
                         reinterpret_cast<const float4*>(encb + (size_t)(sbase + (c + 1) * 4) * Hc), t);

        const float2* ch2 = reinterpret_cast<const float2*>(buf[c & 1]);
        const int s0 = sbase + c * 4;

        // scores: warps 0-3 each compute one row (8 LDS.64 + 8 LDS.64)
        if (w < 4) {
            float d = 0.f;
#pragma unroll
            for (int kk = 0; kk < 8; kk++) {
                int k = lane + kk * 32;
                float2 cv = ch2[w * 256 + k];
                float2 qv = qs2[k];
                d += cv.x * qv.x + cv.y * qv.y;
            }
#pragma unroll
            for (int o = 16; o; o >>= 1) d += __shfl_xor_sync(0xffffffffu, d, o);
            if (lane == 0) {
                float sc = d + cb + smask[c * 4 + w];
                scs[w] = sc;
                g_scr[OFF_ATTN + b * Sc + s0 + w] = sc;
            }
        }
        __syncthreads();

        float cm = fmaxf(fmaxf(scs[0], scs[1]), fmaxf(scs[2], scs[3]));
        float nm = fmaxf(m, cm);
        if (nm > m) {
            float scale = expf(m - nm);
            ax *= scale; ay *= scale; l *= scale;
        }
        if (t < 4) ws[t] = expf(scs[t] - nm);
        __syncthreads();

        float lsum = 0.f;
#pragma unroll
        for (int r = 0; r < 4; r++) {
            float wr = ws[r];
            lsum += wr;
            float2 cv = ch2[r * 256 + t];
            ax += wr * cv.x;
            ay += wr * cv.y;
        }
        l += lsum;
        m = nm;
        // next iteration's first sync protects buf/ws/scs
    }
    const int pid = blockIdx.x;
    if (t == 0) { g_scr[OFF_PARTM + pid] = m; g_scr[OFF_PARTL + pid] = l; }
    reinterpret_cast<float2*>(g_scr + OFF_PARTACC + pid * 512)[t] = make_float2(ax, ay);
}

// ---- combine partials -> ctxraw, zero CTX, top-4, TKLOG: grid 64, block 256 ----
__global__ void __launch_bounds__(256) k_combine(const float* __restrict__ evid) {
    __shared__ float sv[1024];
    __shared__ int pick[4];
    __shared__ float pickv[4];
    __shared__ float wvv[8];
    __shared__ int wii[8];
    const int b = blockIdx.x, t = threadIdx.x;
    dep_sync();   // wait for k_attn partials

    float pm[SLICES], e[SLICES];
    float M = -INFINITY;
#pragma unroll
    for (int p = 0; p < SLICES; p++) { pm[p] = g_scr[OFF_PARTM + b * SLICES + p]; M = fmaxf(M, pm[p]); }
    float L = 0.f;
#pragma unroll
    for (int p = 0; p < SLICES; p++) { e[p] = expf(pm[p] - M); L += g_scr[OFF_PARTL + b * SLICES + p] * e[p]; }
    float invL = 1.f / L;
#pragma unroll
    for (int half = 0; half < 2; half++) {
        int col = t + half * 256;
        float s = 0.f;
#pragma unroll
        for (int p = 0; p < SLICES; p++)
            s += e[p] * g_scr[OFF_PARTACC + (b * SLICES + p) * 512 + col];
        g_scr[OFF_CTXRAW + b * Hc + col] = s * invL;
        g_scr[OFF_CTX + b * Hc + col] = 0.f;
    }
#pragma unroll
    for (int i = 0; i < 4; i++) sv[t + i * 256] = g_scr[OFF_ATTN + b * Sc + t + i * 256];
    __syncthreads();
    for (int round = 0; round < 4; round++) {
        float best = -INFINITY;
        int bi = 0x7fffffff;
#pragma unroll
        for (int u = 0; u < 4; u++) {
            int idx = t * 4 + u;
            bool skip = false;
            for (int rr = 0; rr < round; rr++) skip |= (pick[rr] == idx);
            float v = sv[idx];
            if (!skip && (v > best || (v == best && idx < bi))) { best = v; bi = idx; }
        }
#pragma unroll
        for (int o = 16; o; o >>= 1) {
            float ov = __shfl_xor_sync(0xffffffffu, best, o);
            int   oi = __shfl_xor_sync(0xffffffffu, bi, o);
            if (ov > best || (ov == best && oi < bi)) { best = ov; bi = oi; }
        }
        if ((t & 31) == 0) { wvv[t >> 5] = best; wii[t >> 5] = bi; }
        __syncthreads();
        if (t == 0) {
            float bb = wvv[0]; int bj = wii[0];
            for (int k = 1; k < 8; k++)
                if (wvv[k] > bb || (wvv[k] == bb && wii[k] < bj)) { bb = wvv[k]; bj = wii[k]; }
            pick[round] = bj; pickv[round] = bb;
        }
        __syncthreads();
    }
    if (t < 4) {
        g_scr[OFF_TKLOG + b * 4 + t] = (M - pickv[t]) + logf(L) + evid[b];
        g_tkidx[b * 4 + t] = pick[t];
    }
}

// ================= TAIL: ctx (0-63) | res (64-127, spin) | gather (128-895) ==========
__global__ void __launch_bounds__(256) k_tail(
        const int* __restrict__ esi, const float* __restrict__ prev_scores,
        const float* __restrict__ mask, const float* __restrict__ w2,
        const float* __restrict__ b2, const float* __restrict__ w3,
        float* __restrict__ out) {
    __shared__ float As[32][65];
    __shared__ float Bs[32][65];
    __shared__ int ssels[64];
    __shared__ int ssent[64];
    const int t = threadIdx.x, bid = blockIdx.x;
    const int lane = t & 31, w = t >> 5;

    dep_sync();   // wait for k_combine (CTXRAW, zeroed CTX, TKLOG; ATTN transitively)

    if (bid < 64) {
        // ctx tile: CTX += ctxraw @ w2^T + b2
        int jt = bid >> 3, kt = bid & 7;
        gemm_bt_tile<2, true, false>(g_scr + OFF_CTXRAW, Hc, w2, Hc,
                                     g_scr + OFF_CTX, Hc, b2, kt == 0,
                                     jt * 64, kt * 64, As, Bs);
        __threadfence();
        __syncthreads();
        if (t == 0) atomicAdd(&g_cnt_ctx[jt], 1);
        return;
    }
    if (bid < 128) {
        // res tile: RESULT += CTX @ w3[:, :512]^T ; CTX produced in this kernel -> ldcg + spin
        int j = bid - 64;
        int jt = j >> 3, kt = j & 7;
        if (t == 0) {
            while (__ldcg((const int*)&g_cnt_ctx[kt]) < 8) __nanosleep(64);
        }
        __syncthreads();
        gemm_bt_tile<2, true, true>(g_scr + OFF_CTX, Hc, w3, 1024,
                                    g_scr + OFF_RESULT, Hc, nullptr, false,
                                    jt * 64, kt * 64, As, Bs);
        __threadfence();
        __syncthreads();
        if (t == 0) atomicAdd(&g_cnt_res, 1);
        return;
    }

    // ---- gather: blocks 128..895 (768), each thread handles i and i+196608 ----
    const int gb = bid - 128;

    // beam selection (redundant per block; 8 warps x 2 batches)
#pragma unroll
    for (int it2 = 0; it2 < 2; it2++) {
        int wb = w * 2 + it2;
        float v = (lane < 16) ? g_scr[OFF_TKLOG + wb * 16 + lane] : INFINITY;
        int rank = 0;
#pragma unroll
        for (int jj = 0; jj < 16; jj++) {
            float vj = __shfl_sync(0xffffffffu, v, jj);
            rank += (vj < v) || (vj == v && jj < lane);
        }
        if (lane < 16 && rank < 4) {
            int k = wb * 4 + rank;
            int s = wb * 4 + (lane >> 2);
            int rr = lane & 3;
            int sent = g_tkidx[s * 4 + rr];
            ssels[k] = s;
            ssent[k] = sent;
            if (gb == 0) {
                out[O_SCORES + k] = v;
                out[O_IDX + k * 4 + 0] = (float)esi[s * 3 + 0];
                out[O_IDX + k * 4 + 1] = (float)esi[s * 3 + 1];
                out[O_IDX + k * 4 + 2] = (float)esi[s * 3 + 2];
                out[O_IDX + k * 4 + 3] = (float)sent;
            }
        }
    }

    // blocks touching RESULT (gb < 128 -> i < 32768) wait for all res tiles
    if (gb < 128) {
        if (t == 0) {
            while (__ldcg((const int*)&g_cnt_res) < 64) __nanosleep(64);
        }
    }
    __syncthreads();

#pragma unroll
    for (int half = 0; half < 2; half++) {
        int i = gb * 256 + t + half * 196608;
        if (i < 32768) {
            int bi = i >> 9, jj = i & 511;
            out[O_RESULT + i] = __ldcg(&g_scr[OFF_RESULT + ssels[bi] * 512 + jj]);
        } else if (i < 65536) {
            int jj = i - 32768;
            out[O_HIDDEN + jj] = g_scr[OFF_HNEW + ssels[jj >> 9] * 512 + (jj & 511)];
        } else if (i < 327680) {
            int jj = i - 65536;
            int p = jj >> 16;
            int rem = jj & 65535;
            int bi = rem >> 10, scol = rem & 1023;
            int s = ssels[bi];
            float v = (p < 3) ? prev_scores[p * 65536 + s * 1024 + scol]
                              : g_scr[OFF_ATTN + s * 1024 + scol];
            out[O_ATTNS + jj] = v;
        } else {
            int jj = i - 327680;
            int bi = jj >> 10, scol = jj & 1023;
            int s = ssels[bi];
            float v = (scol == ssent[bi]) ? NEG_INF_VAL : mask[s * 1024 + scol];
            out[O_MASK + jj] = v;
        }
    }
}

// ---------------- launch helpers ----------------
static inline void launch_pdl(const void* func, dim3 grid, dim3 block, void** args) {
    cudaLaunchConfig_t cfg = {};
    cfg.gridDim = grid;
    cfg.blockDim = block;
    cfg.dynamicSmemBytes = 0;
    cfg.stream = 0;
    cudaLaunchAttribute attr[1];
    attr[0].id = cudaLaunchAttributeProgrammaticStreamSerialization;
    attr[0].val.programmaticStreamSerializationAllowed = 1;
    cfg.attrs = attr;
    cfg.numAttrs = 1;
    cudaLaunchKernelExC(&cfg, func, args);
}

extern "C" void kernel_launch(void* const* d_in, const int* in_sizes, int n_in,
                              void* d_out, int out_size) {
    const float* last_hidden = (const float*)d_in[0];
    const float* dec_inputs  = (const float*)d_in[1];
    const float* enc         = (const float*)d_in[2];
    const float* prev_scores = (const float*)d_in[3];
    const float* mask        = (const float*)d_in[4];
    const float* evid        = (const float*)d_in[5];
    const int*   esi         = (const int*)d_in[6];
    const float* w1  = (const float*)d_in[7];
    const float* b1  = (const float*)d_in[8];
    const float* w2  = (const float*)d_in[9];
    const float* b2  = (const float*)d_in[10];
    const float* w3  = (const float*)d_in[11];
    const float* b3  = (const float*)d_in[12];
    const float* wih = (const float*)d_in[13];
    const float* whh = (const float*)d_in[14];
    const float* bih = (const float*)d_in[15];
    const float* bhh = (const float*)d_in[16];
    float* out = (float*)d_out;

    k_gru<<<dim3(24, KS, 2), 256>>>(dec_inputs, last_hidden, wih, whh);

    { void* a[] = {(void*)&last_hidden, (void*)&bih, (void*)&bhh, (void*)&b1};
      launch_pdl((const void*)k_gate, dim3(64), dim3(512), a); }
    { void* a[] = {(void*)&w1, (void*)&w3, (void*)&b3};
      launch_pdl((const void*)k_q2, dim3(8, KS, 2), dim3(256), a); }
    { void* a[] = {(void*)&enc, (void*)&mask};
      launch_pdl((const void*)k_attn, dim3(1024), dim3(256), a); }
    { void* a[] = {(void*)&evid};
      launch_pdl((const void*)k_combine, dim3(64), dim3(256), a); }
    { void* a[] = {(void*)&esi, (void*)&prev_scores, (void*)&mask,
                   (void*)&w2, (void*)&b2, (void*)&w3, (void*)&out};
      launch_pdl((const void*)k_tail, dim3(896), dim3(256), a); }
}